// round 1
// baseline (speedup 1.0000x reference)
#include <cuda_runtime.h>
#include <math_constants.h>

// Problem: B=8, S=2048, D=1024 fused attention, fp32.
//   wq = q @ Wq^T + bq          (3x GEMM-NT, M=B*S=16384, N=1024, K=1024)
//   att = wq @ wk^T / 32 + mask (batched GEMM-NT, M=N=2048, K=1024)
//   att = softmax_rows(att)
//   out = att @ wv              (batched GEMM-NN, M=2048, N=1024, K=2048)

#define BM 128
#define BN 128
#define BK 16

static __device__ float g_wq[8 * 2048 * 1024];
static __device__ float g_wk[8 * 2048 * 1024];
static __device__ float g_wv[8 * 2048 * 1024];
static __device__ float g_att[8ull * 2048ull * 2048ull];

// ---------------------------------------------------------------------------
// C = alpha * (A @ B^T) [+ bias broadcast over rows] [+ addmat (M x N)]
// A: [M, K] row-major (batch stride sA)
// B: [N, K] row-major (batch stride sB)   -> C[m,n] = sum_k A[m,k] * B[n,k]
// ---------------------------------------------------------------------------
__global__ __launch_bounds__(256, 2)
void gemm_nt(const float* __restrict__ Ag, const float* __restrict__ Bg,
             float* __restrict__ Cg,
             int M, int N, int K,
             long long sA, long long sB, long long sC,
             float alpha,
             const float* __restrict__ bias,
             const float* __restrict__ addmat)
{
    const float* A = Ag + (long long)blockIdx.z * sA;
    const float* B = Bg + (long long)blockIdx.z * sB;
    float*       C = Cg + (long long)blockIdx.z * sC;

    const int m0 = blockIdx.y * BM;
    const int n0 = blockIdx.x * BN;

    __shared__ float As[BK][BM];
    __shared__ float Bs[BK][BN];

    const int tid = threadIdx.x;
    const int tx = tid & 15;        // 0..15 -> n microtile
    const int ty = tid >> 4;        // 0..15 -> m microtile
    const int lr = tid >> 2;        // 0..63 load row
    const int lc = (tid & 3) << 2;  // 0,4,8,12 load k-offset

    float acc[8][8];
#pragma unroll
    for (int i = 0; i < 8; ++i)
#pragma unroll
        for (int j = 0; j < 8; ++j) acc[i][j] = 0.f;

    for (int k0 = 0; k0 < K; k0 += BK) {
#pragma unroll
        for (int p = 0; p < 2; ++p) {
            const int r = lr + p * 64;
            float4 va = *(const float4*)(&A[(long long)(m0 + r) * K + k0 + lc]);
            As[lc + 0][r] = va.x;
            As[lc + 1][r] = va.y;
            As[lc + 2][r] = va.z;
            As[lc + 3][r] = va.w;
            float4 vb = *(const float4*)(&B[(long long)(n0 + r) * K + k0 + lc]);
            Bs[lc + 0][r] = vb.x;
            Bs[lc + 1][r] = vb.y;
            Bs[lc + 2][r] = vb.z;
            Bs[lc + 3][r] = vb.w;
        }
        __syncthreads();
#pragma unroll
        for (int kk = 0; kk < BK; ++kk) {
            float4 a0 = *(const float4*)&As[kk][ty * 8];
            float4 a1 = *(const float4*)&As[kk][ty * 8 + 4];
            float4 b0 = *(const float4*)&Bs[kk][tx * 8];
            float4 b1 = *(const float4*)&Bs[kk][tx * 8 + 4];
            float a[8] = {a0.x, a0.y, a0.z, a0.w, a1.x, a1.y, a1.z, a1.w};
            float b[8] = {b0.x, b0.y, b0.z, b0.w, b1.x, b1.y, b1.z, b1.w};
#pragma unroll
            for (int i = 0; i < 8; ++i)
#pragma unroll
                for (int j = 0; j < 8; ++j)
                    acc[i][j] = fmaf(a[i], b[j], acc[i][j]);
        }
        __syncthreads();
    }

#pragma unroll
    for (int i = 0; i < 8; ++i) {
        const int m = m0 + ty * 8 + i;
#pragma unroll
        for (int j = 0; j < 8; j += 4) {
            const int n = n0 + tx * 8 + j;
            float4 r;
            r.x = acc[i][j + 0] * alpha;
            r.y = acc[i][j + 1] * alpha;
            r.z = acc[i][j + 2] * alpha;
            r.w = acc[i][j + 3] * alpha;
            if (bias) {
                float4 bb = *(const float4*)&bias[n];
                r.x += bb.x; r.y += bb.y; r.z += bb.z; r.w += bb.w;
            }
            if (addmat) {
                float4 mm = *(const float4*)&addmat[(long long)m * N + n];
                r.x += mm.x; r.y += mm.y; r.z += mm.z; r.w += mm.w;
            }
            *(float4*)&C[(long long)m * N + n] = r;
        }
    }
}

// ---------------------------------------------------------------------------
// C = A @ B    A: [M, K] row-major (stride sA), B: [K, N] row-major (stride sB)
// ---------------------------------------------------------------------------
__global__ __launch_bounds__(256, 2)
void gemm_nn(const float* __restrict__ Ag, const float* __restrict__ Bg,
             float* __restrict__ Cg,
             int M, int N, int K,
             long long sA, long long sB, long long sC)
{
    const float* A = Ag + (long long)blockIdx.z * sA;
    const float* B = Bg + (long long)blockIdx.z * sB;
    float*       C = Cg + (long long)blockIdx.z * sC;

    const int m0 = blockIdx.y * BM;
    const int n0 = blockIdx.x * BN;

    __shared__ float As[BK][BM];
    __shared__ float Bs[BK][BN];

    const int tid = threadIdx.x;
    const int tx = tid & 15;
    const int ty = tid >> 4;
    const int lr = tid >> 2;        // 0..63
    const int lc = (tid & 3) << 2;  // 0,4,8,12
    const int bn = (tid & 31) << 2; // 0..124
    const int bk = tid >> 5;        // 0..7

    float acc[8][8];
#pragma unroll
    for (int i = 0; i < 8; ++i)
#pragma unroll
        for (int j = 0; j < 8; ++j) acc[i][j] = 0.f;

    for (int k0 = 0; k0 < K; k0 += BK) {
#pragma unroll
        for (int p = 0; p < 2; ++p) {
            const int r = lr + p * 64;
            float4 va = *(const float4*)(&A[(long long)(m0 + r) * K + k0 + lc]);
            As[lc + 0][r] = va.x;
            As[lc + 1][r] = va.y;
            As[lc + 2][r] = va.z;
            As[lc + 3][r] = va.w;
            const int kk = bk + p * 8;
            float4 vb = *(const float4*)(&B[(long long)(k0 + kk) * N + n0 + bn]);
            *(float4*)&Bs[kk][bn] = vb;
        }
        __syncthreads();
#pragma unroll
        for (int kk = 0; kk < BK; ++kk) {
            float4 a0 = *(const float4*)&As[kk][ty * 8];
            float4 a1 = *(const float4*)&As[kk][ty * 8 + 4];
            float4 b0 = *(const float4*)&Bs[kk][tx * 8];
            float4 b1 = *(const float4*)&Bs[kk][tx * 8 + 4];
            float a[8] = {a0.x, a0.y, a0.z, a0.w, a1.x, a1.y, a1.z, a1.w};
            float b[8] = {b0.x, b0.y, b0.z, b0.w, b1.x, b1.y, b1.z, b1.w};
#pragma unroll
            for (int i = 0; i < 8; ++i)
#pragma unroll
                for (int j = 0; j < 8; ++j)
                    acc[i][j] = fmaf(a[i], b[j], acc[i][j]);
        }
        __syncthreads();
    }

#pragma unroll
    for (int i = 0; i < 8; ++i) {
        const int m = m0 + ty * 8 + i;
#pragma unroll
        for (int j = 0; j < 8; j += 4) {
            const int n = n0 + tx * 8 + j;
            float4 r = make_float4(acc[i][j + 0], acc[i][j + 1],
                                   acc[i][j + 2], acc[i][j + 3]);
            *(float4*)&C[(long long)m * N + n] = r;
        }
    }
}

// ---------------------------------------------------------------------------
// In-place row softmax, rows of exactly 2048 floats, one CTA (256 thr) per row.
// ---------------------------------------------------------------------------
__global__ __launch_bounds__(256)
void softmax2048(float* __restrict__ att)
{
    float* p = att + (long long)blockIdx.x * 2048;
    const int tid = threadIdx.x;
    const int lane = tid & 31;
    const int warp = tid >> 5;

    float4 v0 = ((const float4*)p)[tid];
    float4 v1 = ((const float4*)p)[tid + 256];
    float x[8] = {v0.x, v0.y, v0.z, v0.w, v1.x, v1.y, v1.z, v1.w};

    __shared__ float sm[8];

    // --- block max ---
    float mx = x[0];
#pragma unroll
    for (int i = 1; i < 8; ++i) mx = fmaxf(mx, x[i]);
#pragma unroll
    for (int o = 16; o > 0; o >>= 1)
        mx = fmaxf(mx, __shfl_xor_sync(0xffffffffu, mx, o));
    if (lane == 0) sm[warp] = mx;
    __syncthreads();
    if (tid == 0) {
        float t = sm[0];
#pragma unroll
        for (int i = 1; i < 8; ++i) t = fmaxf(t, sm[i]);
        sm[0] = t;
    }
    __syncthreads();
    mx = sm[0];
    __syncthreads();

    // --- exp + block sum ---
    float s = 0.f;
#pragma unroll
    for (int i = 0; i < 8; ++i) {
        x[i] = __expf(x[i] - mx);
        s += x[i];
    }
#pragma unroll
    for (int o = 16; o > 0; o >>= 1)
        s += __shfl_xor_sync(0xffffffffu, s, o);
    if (lane == 0) sm[warp] = s;
    __syncthreads();
    if (tid == 0) {
        float t = 0.f;
#pragma unroll
        for (int i = 0; i < 8; ++i) t += sm[i];
        sm[0] = t;
    }
    __syncthreads();
    const float inv = 1.f / sm[0];

    v0 = make_float4(x[0] * inv, x[1] * inv, x[2] * inv, x[3] * inv);
    v1 = make_float4(x[4] * inv, x[5] * inv, x[6] * inv, x[7] * inv);
    ((float4*)p)[tid] = v0;
    ((float4*)p)[tid + 256] = v1;
}

// ---------------------------------------------------------------------------

extern "C" void kernel_launch(void* const* d_in, const int* in_sizes, int n_in,
                              void* d_out, int out_size)
{
    const float* q    = (const float*)d_in[0];
    const float* k    = (const float*)d_in[1];
    const float* v    = (const float*)d_in[2];
    const float* mask = (const float*)d_in[3];
    const float* Wq   = (const float*)d_in[4];
    const float* bq   = (const float*)d_in[5];
    const float* Wk   = (const float*)d_in[6];
    const float* bk   = (const float*)d_in[7];
    const float* Wv   = (const float*)d_in[8];
    const float* bv   = (const float*)d_in[9];
    float* out = (float*)d_out;

    float *wqp, *wkp, *wvp, *attp;
    cudaGetSymbolAddress((void**)&wqp, g_wq);
    cudaGetSymbolAddress((void**)&wkp, g_wk);
    cudaGetSymbolAddress((void**)&wvp, g_wv);
    cudaGetSymbolAddress((void**)&attp, g_att);

    const int B = 8, S = 2048, D = 1024;
    const long long pStride = (long long)S * D;        // 2048*1024
    const long long aStride = (long long)S * S;        // 2048*2048

    // Projections: [B*S, D] @ [D, D]^T + bias
    {
        dim3 grid(D / BN, (B * S) / BM, 1);
        gemm_nt<<<grid, 256>>>(q, Wq, wqp, B * S, D, D, 0, 0, 0, 1.f, bq, nullptr);
        gemm_nt<<<grid, 256>>>(k, Wk, wkp, B * S, D, D, 0, 0, 0, 1.f, bk, nullptr);
        gemm_nt<<<grid, 256>>>(v, Wv, wvp, B * S, D, D, 0, 0, 0, 1.f, bv, nullptr);
    }

    // Scores: att[b] = wq[b] @ wk[b]^T / 32 + mask
    {
        dim3 grid(S / BN, S / BM, B);
        gemm_nt<<<grid, 256>>>(wqp, wkp, attp, S, S, D,
                               pStride, pStride, aStride,
                               1.f / 32.f, nullptr, mask);
    }

    // Softmax over keys
    softmax2048<<<B * S, 256>>>(attp);

    // Output: out[b] = att[b] @ wv[b]
    {
        dim3 grid(D / BN, S / BM, B);
        gemm_nn<<<grid, 256>>>(attp, wvp, out, S, D, S,
                               aStride, pStride, pStride);
    }
}

// round 3
// speedup vs baseline: 2.6487x; 2.6487x over previous
#include <cuda_runtime.h>
#include <cstdint>

// ===========================================================================
// B=8, S=2048, D=1024 attention, fp32 in/out, tf32 mma.sync GEMM cores.
// (tcgen05 unavailable: harness compiles PTX at compute_103, no 'a' feature.)
//   wq = q @ Wq^T + bq            NT  M=16384 N=1024 K=1024
//   att = wq @ wk^T /32 + mask    NT  M=2048  N=2048 K=1024  (batched x8)
//   att = softmax rows
//   out = att @ wvT^T             NT  M=2048  N=1024 K=2048  (wvT = wv^T)
// ===========================================================================

static __device__ float g_wq [8ull * 2048ull * 1024ull];
static __device__ float g_wk [8ull * 2048ull * 1024ull];
static __device__ float g_wv [8ull * 2048ull * 1024ull];
static __device__ float g_wvT[8ull * 1024ull * 2048ull];
static __device__ float g_att[8ull * 2048ull * 2048ull];

__device__ __forceinline__ uint32_t f2tf32(float x) {
    uint32_t r;
    asm("cvt.rna.tf32.f32 %0, %1;" : "=r"(r) : "f"(x));
    return r;
}

__device__ __forceinline__ void mma_tf32(float* d, const uint32_t* a,
                                         const uint32_t* b) {
    asm volatile(
        "mma.sync.aligned.m16n8k8.row.col.f32.tf32.tf32.f32 "
        "{%0,%1,%2,%3}, {%4,%5,%6,%7}, {%8,%9}, {%0,%1,%2,%3};\n"
        : "+f"(d[0]), "+f"(d[1]), "+f"(d[2]), "+f"(d[3])
        : "r"(a[0]), "r"(a[1]), "r"(a[2]), "r"(a[3]),
          "r"(b[0]), "r"(b[1]));
}

// ---------------------------------------------------------------------------
// C = alpha * (A @ B^T) [+ bias over cols] [+ addmat rows], tf32 mma.sync
// A: [M,K] row-major (+z*sA), B: [N,K] row-major (+z*sB), C: [M,N] (+z*sC)
// M%128==0, N%128==0, K%32==0.
// CTA 128x128x(K chunks of 32); 4 warps, warp tile 64x64.
//
// SMEM fragment-packed layouts (uint32 words), double buffered:
//  A: [buf][ks(4)][mtile(8)][lane(32)][reg(4)]  (lane stored as lane^ks)
//  B: [buf][ks(4)][ntile(16)][lane(32)][reg(2)] (lane stored as lane^ks)
// A element (m,k): mt=m>>4, r=m&15, ks=k>>3, lane=(r&7)*4+(k&3),
//                  reg=(r>>3)|((k>>2&1)<<1)
// B element (n,k): nt=n>>3, lane=(n&7)*4+(k&3), reg=(k>>2)&1
// ---------------------------------------------------------------------------
__global__ __launch_bounds__(128, 2)
void gemm_tc_nt(const float* __restrict__ Ag, const float* __restrict__ Bg,
                float* __restrict__ Cg,
                int M, int N, int K,
                long long sA, long long sB, long long sC,
                float alpha,
                const float* __restrict__ bias,
                const float* __restrict__ addmat, int ldAdd)
{
    extern __shared__ uint32_t sm[];
    uint32_t* smA = sm;          // 2 * 4096 words
    uint32_t* smB = sm + 8192;   // 2 * 4096 words

    const int tid  = threadIdx.x;
    const int lane = tid & 31;
    const int wid  = tid >> 5;
    const int wm   = wid & 1;    // warp m half (64 rows)
    const int wn   = wid >> 1;   // warp n half (64 cols)

    const float* A = Ag + (long long)blockIdx.z * sA;
    const float* B = Bg + (long long)blockIdx.z * sB;
    float*       C = Cg + (long long)blockIdx.z * sC;

    const int m0 = blockIdx.y * 128;
    const int n0 = blockIdx.x * 128;

    float acc[4][8][4];
#pragma unroll
    for (int i = 0; i < 4; ++i)
#pragma unroll
        for (int j = 0; j < 8; ++j)
#pragma unroll
            for (int l = 0; l < 4; ++l) acc[i][j][l] = 0.f;

    const int KT = K / 32;

    auto stage = [&](int it, int buf) {
        const float* Ab = A + (long long)m0 * K + it * 32;
        uint32_t* sA_ = smA + buf * 4096;
#pragma unroll
        for (int i = 0; i < 8; ++i) {
            const int f = tid + 128 * i;
            const int m = f >> 3;
            const int c0 = (f & 7) << 2;
            const float4 v = *(const float4*)(Ab + (long long)m * K + c0);
            const int mt = m >> 4, r = m & 15;
            const int ks = c0 >> 3, chi = (c0 >> 2) & 1;
            const int W = ((ks * 8 + mt) * 32 + (r & 7) * 4) * 4 +
                          ((r >> 3) | (chi << 1));
            sA_[W + ((0 ^ ks) << 2)] = f2tf32(v.x);
            sA_[W + ((1 ^ ks) << 2)] = f2tf32(v.y);
            sA_[W + ((2 ^ ks) << 2)] = f2tf32(v.z);
            sA_[W + ((3 ^ ks) << 2)] = f2tf32(v.w);
        }
        const float* Bb = B + (long long)n0 * K + it * 32;
        uint32_t* sB_ = smB + buf * 4096;
#pragma unroll
        for (int i = 0; i < 8; ++i) {
            const int f = tid + 128 * i;
            const int n = f >> 3;
            const int c0 = (f & 7) << 2;
            const float4 v = *(const float4*)(Bb + (long long)n * K + c0);
            const int nt = n >> 3, nn = n & 7;
            const int ks = c0 >> 3, chi = (c0 >> 2) & 1;
            const int W = ((ks * 16 + nt) * 32 + nn * 4) * 2 + chi;
            sB_[W + ((0 ^ ks) << 1)] = f2tf32(v.x);
            sB_[W + ((1 ^ ks) << 1)] = f2tf32(v.y);
            sB_[W + ((2 ^ ks) << 1)] = f2tf32(v.z);
            sB_[W + ((3 ^ ks) << 1)] = f2tf32(v.w);
        }
    };

    stage(0, 0);
    __syncthreads();

    for (int it = 0; it < KT; ++it) {
        if (it + 1 < KT) stage(it + 1, (it + 1) & 1);

        const uint32_t* sA_ = smA + (it & 1) * 4096;
        const uint32_t* sB_ = smB + (it & 1) * 4096;
#pragma unroll
        for (int ks = 0; ks < 4; ++ks) {
            const int lx = lane ^ ks;
            uint32_t af[4][4];
            uint32_t bf[8][2];
#pragma unroll
            for (int mi = 0; mi < 4; ++mi) {
                const uint4 t = *(const uint4*)
                    &sA_[((ks * 8 + wm * 4 + mi) * 32 + lx) * 4];
                af[mi][0] = t.x; af[mi][1] = t.y;
                af[mi][2] = t.z; af[mi][3] = t.w;
            }
#pragma unroll
            for (int ni = 0; ni < 8; ++ni) {
                const uint2 t = *(const uint2*)
                    &sB_[((ks * 16 + wn * 8 + ni) * 32 + lx) * 2];
                bf[ni][0] = t.x; bf[ni][1] = t.y;
            }
#pragma unroll
            for (int mi = 0; mi < 4; ++mi)
#pragma unroll
                for (int ni = 0; ni < 8; ++ni)
                    mma_tf32(acc[mi][ni], af[mi], bf[ni]);
        }
        __syncthreads();
    }

    // ---- epilogue ----
    const int mb = m0 + wm * 64 + (lane >> 2);
    const int nb = n0 + wn * 64 + (lane & 3) * 2;
#pragma unroll
    for (int mi = 0; mi < 4; ++mi) {
#pragma unroll
        for (int half = 0; half < 2; ++half) {
            const int m = mb + mi * 16 + half * 8;
            float* crow = C + (long long)m * N;
            const float* arow =
                addmat ? addmat + (long long)m * ldAdd : nullptr;
#pragma unroll
            for (int ni = 0; ni < 8; ++ni) {
                const int n = nb + ni * 8;
                float2 o;
                o.x = acc[mi][ni][half * 2 + 0] * alpha;
                o.y = acc[mi][ni][half * 2 + 1] * alpha;
                if (bias)   { o.x += bias[n];  o.y += bias[n + 1]; }
                if (arow)   { o.x += arow[n];  o.y += arow[n + 1]; }
                *(float2*)(crow + n) = o;
            }
        }
    }
}

// ---------------------------------------------------------------------------
// per-batch transpose: out[b][d][s] = in[b][s][d]   (S=2048, D=1024)
// ---------------------------------------------------------------------------
__global__ __launch_bounds__(256)
void transpose_sd(const float* __restrict__ in, float* __restrict__ out)
{
    __shared__ float tile[32][33];
    const int S = 2048, D = 1024;
    const long long bo = (long long)blockIdx.z * S * D;
    const int d0 = blockIdx.x * 32;
    const int s0 = blockIdx.y * 32;
    const int tx = threadIdx.x & 31;
    const int ty = threadIdx.x >> 5;
#pragma unroll
    for (int i = 0; i < 4; ++i)
        tile[ty + i * 8][tx] = in[bo + (long long)(s0 + ty + i * 8) * D + d0 + tx];
    __syncthreads();
#pragma unroll
    for (int i = 0; i < 4; ++i)
        out[bo + (long long)(d0 + ty + i * 8) * S + s0 + tx] = tile[tx][ty + i * 8];
}

// ---------------------------------------------------------------------------
// In-place row softmax, rows of 2048 floats, one CTA (256 thr) per row.
// ---------------------------------------------------------------------------
__global__ __launch_bounds__(256)
void softmax2048(float* __restrict__ att)
{
    float* p = att + (long long)blockIdx.x * 2048;
    const int tid = threadIdx.x;
    const int lane = tid & 31;
    const int warp = tid >> 5;

    float4 v0 = ((const float4*)p)[tid];
    float4 v1 = ((const float4*)p)[tid + 256];
    float x[8] = {v0.x, v0.y, v0.z, v0.w, v1.x, v1.y, v1.z, v1.w};

    __shared__ float sm[8];

    float mx = x[0];
#pragma unroll
    for (int i = 1; i < 8; ++i) mx = fmaxf(mx, x[i]);
#pragma unroll
    for (int o = 16; o > 0; o >>= 1)
        mx = fmaxf(mx, __shfl_xor_sync(0xffffffffu, mx, o));
    if (lane == 0) sm[warp] = mx;
    __syncthreads();
    if (tid == 0) {
        float t = sm[0];
#pragma unroll
        for (int i = 1; i < 8; ++i) t = fmaxf(t, sm[i]);
        sm[0] = t;
    }
    __syncthreads();
    mx = sm[0];
    __syncthreads();

    float s = 0.f;
#pragma unroll
    for (int i = 0; i < 8; ++i) {
        x[i] = __expf(x[i] - mx);
        s += x[i];
    }
#pragma unroll
    for (int o = 16; o > 0; o >>= 1)
        s += __shfl_xor_sync(0xffffffffu, s, o);
    if (lane == 0) sm[warp] = s;
    __syncthreads();
    if (tid == 0) {
        float t = 0.f;
#pragma unroll
        for (int i = 0; i < 8; ++i) t += sm[i];
        sm[0] = t;
    }
    __syncthreads();
    const float inv = 1.f / sm[0];

    v0 = make_float4(x[0] * inv, x[1] * inv, x[2] * inv, x[3] * inv);
    v1 = make_float4(x[4] * inv, x[5] * inv, x[6] * inv, x[7] * inv);
    ((float4*)p)[tid] = v0;
    ((float4*)p)[tid + 256] = v1;
}

// ---------------------------------------------------------------------------

extern "C" void kernel_launch(void* const* d_in, const int* in_sizes, int n_in,
                              void* d_out, int out_size)
{
    const float* q    = (const float*)d_in[0];
    const float* k    = (const float*)d_in[1];
    const float* v    = (const float*)d_in[2];
    const float* mask = (const float*)d_in[3];
    const float* Wq   = (const float*)d_in[4];
    const float* bq   = (const float*)d_in[5];
    const float* Wk   = (const float*)d_in[6];
    const float* bk   = (const float*)d_in[7];
    const float* Wv   = (const float*)d_in[8];
    const float* bv   = (const float*)d_in[9];
    float* out = (float*)d_out;

    float *wqp, *wkp, *wvp, *wvtp, *attp;
    cudaGetSymbolAddress((void**)&wqp,  g_wq);
    cudaGetSymbolAddress((void**)&wkp,  g_wk);
    cudaGetSymbolAddress((void**)&wvp,  g_wv);
    cudaGetSymbolAddress((void**)&wvtp, g_wvT);
    cudaGetSymbolAddress((void**)&attp, g_att);

    const int SMEM = 16384 * 4;   // 64 KB
    static int configured = 0;
    if (!configured) {
        cudaFuncSetAttribute(gemm_tc_nt,
                             cudaFuncAttributeMaxDynamicSharedMemorySize, SMEM);
        configured = 1;
    }

    const int B = 8, S = 2048, D = 1024;
    const long long pS = (long long)S * D;   // projection batch stride
    const long long tS = (long long)D * S;   // wvT batch stride
    const long long aS = (long long)S * S;   // attention batch stride

    // Projections: [16384,1024] @ [1024,1024]^T + bias
    {
        dim3 grid(D / 128, (B * S) / 128, 1);
        gemm_tc_nt<<<grid, 128, SMEM>>>(q, Wq, wqp, B * S, D, D, 0, 0, 0,
                                        1.f, bq, nullptr, 0);
        gemm_tc_nt<<<grid, 128, SMEM>>>(k, Wk, wkp, B * S, D, D, 0, 0, 0,
                                        1.f, bk, nullptr, 0);
        gemm_tc_nt<<<grid, 128, SMEM>>>(v, Wv, wvp, B * S, D, D, 0, 0, 0,
                                        1.f, bv, nullptr, 0);
    }

    // wvT[b] = wv[b]^T
    {
        dim3 grid(D / 32, S / 32, B);
        transpose_sd<<<grid, 256>>>(wvp, wvtp);
    }

    // Scores: att[b] = wq[b] @ wk[b]^T / 32 + mask
    {
        dim3 grid(S / 128, S / 128, B);
        gemm_tc_nt<<<grid, 128, SMEM>>>(wqp, wkp, attp, S, S, D,
                                        pS, pS, aS,
                                        1.f / 32.f, nullptr, mask, S);
    }

    // Softmax over keys
    softmax2048<<<B * S, 256>>>(attp);

    // Output: out[b] = att[b] @ wv[b] = att[b] @ wvT[b]^T
    {
        dim3 grid(D / 128, S / 128, B);
        gemm_tc_nt<<<grid, 128, SMEM>>>(attp, wvtp, out, S, D, S,
                                        aS, tS, pS, 1.f, nullptr, nullptr, 0);
    }
}

// round 8
// speedup vs baseline: 7.5462x; 2.8490x over previous
#include <cuda_runtime.h>
#include <cuda_fp16.h>
#include <cstdint>

// ===========================================================================
// B=8, S=2048, D=1024 attention. fp16 mma.sync(m16n8k16) + cp.async pipeline.
//   convert q,k,v,W* to fp16
//   wq = q @ Wq^T + b   (one z=3 launch, M=16384 N=1024 K=1024) -> fp16
//   wvT = wv^T
//   att = (wq @ wk^T)/32 + mask  -> fp16 (raw scores)
//   softmax rows (fp32 math, fp16 I/O)
//   out = att @ wvT^T  -> fp32
// ===========================================================================

static __device__ __half g_qh [8ull * 2048ull * 1024ull];
static __device__ __half g_kh [8ull * 2048ull * 1024ull];
static __device__ __half g_vh [8ull * 2048ull * 1024ull];
static __device__ __half g_Wqh[1024ull * 1024ull];
static __device__ __half g_Wkh[1024ull * 1024ull];
static __device__ __half g_Wvh[1024ull * 1024ull];
static __device__ __half g_wqh[8ull * 2048ull * 1024ull];
static __device__ __half g_wkh[8ull * 2048ull * 1024ull];
static __device__ __half g_wvh[8ull * 2048ull * 1024ull];
static __device__ __half g_wvT[8ull * 1024ull * 2048ull];
static __device__ __half g_att[8ull * 2048ull * 2048ull];

__device__ __forceinline__ uint32_t smem_u32(const void* p) {
    uint32_t a;
    asm("{ .reg .u64 t; cvta.to.shared.u64 t, %1; cvt.u32.u64 %0, t; }"
        : "=r"(a) : "l"(p));
    return a;
}

__device__ __forceinline__ void cp16(uint32_t s, const void* g) {
    asm volatile("cp.async.cg.shared.global [%0], [%1], 16;" :: "r"(s), "l"(g));
}
#define CP_COMMIT() asm volatile("cp.async.commit_group;" ::: "memory")
#define CP_WAIT1()  asm volatile("cp.async.wait_group 1;" ::: "memory")

#define LDSM_X4(r, a)                                                        \
    asm volatile("ldmatrix.sync.aligned.m8n8.x4.shared.b16 {%0,%1,%2,%3}, [%4];" \
        : "=r"((r)[0]), "=r"((r)[1]), "=r"((r)[2]), "=r"((r)[3]) : "r"(a))

__device__ __forceinline__ void mma_f16(float* d, const uint32_t* a,
                                        const uint32_t* b) {
    asm volatile(
        "mma.sync.aligned.m16n8k16.row.col.f32.f16.f16.f32 "
        "{%0,%1,%2,%3}, {%4,%5,%6,%7}, {%8,%9}, {%0,%1,%2,%3};\n"
        : "+f"(d[0]), "+f"(d[1]), "+f"(d[2]), "+f"(d[3])
        : "r"(a[0]), "r"(a[1]), "r"(a[2]), "r"(a[3]), "r"(b[0]), "r"(b[1]));
}

// SMEM: 3 stages x (A 16KB + B 16KB) = 96 KB
static constexpr int STAGE  = 32768;
static constexpr int SMEMSZ = 3 * STAGE;

// ---------------------------------------------------------------------------
// Core: C = alpha*(A @ B^T) [+bias cols] [+mask]; A:[*,K] B:[*,K] fp16 NT.
// CTA 128x128, warp 64x64, K-chunk 64, 3-stage cp.async ring.
// smem row layout: 128 rows x 128B (64 halves), 16B chunk c at (c ^ (row&7)).
// B stored [n][k] row-major == col-major KxN for mma.row.col, so BOTH A and
// B fragments come from NON-trans ldmatrix (each reg = 2 consecutive k).
// ---------------------------------------------------------------------------
template <bool HOUT>
__device__ __forceinline__ void gemm_core(
    const __half* __restrict__ A, const __half* __restrict__ B,
    void* __restrict__ Cv, int N, int K, float alpha,
    const float* __restrict__ bias,
    const float* __restrict__ mask, int ldMask,
    int m0, int n0)
{
    extern __shared__ char smem[];
    const uint32_t sb = smem_u32(smem);
    const int tid  = threadIdx.x;
    const int lane = tid & 31;
    const int wid  = tid >> 5;
    const int wm   = wid & 1;
    const int wn   = wid >> 1;

    float acc[4][8][4];
#pragma unroll
    for (int i = 0; i < 4; ++i)
#pragma unroll
        for (int j = 0; j < 8; ++j)
#pragma unroll
            for (int l = 0; l < 4; ++l) acc[i][j][l] = 0.f;

    const int KT = K >> 6;

    auto stage = [&](int it) {
        const int buf = it % 3;
        const uint32_t sA = sb + buf * STAGE;
        const uint32_t sB = sA + 16384;
        const __half* Ab = A + (size_t)m0 * K + it * 64;
        const __half* Bb = B + (size_t)n0 * K + it * 64;
#pragma unroll
        for (int i = 0; i < 8; ++i) {
            const int f = tid + (i << 7);
            const int r = f >> 3, c = f & 7;
            const uint32_t off = r * 128 + ((c ^ (r & 7)) << 4);
            cp16(sA + off, Ab + (size_t)r * K + c * 8);
            cp16(sB + off, Bb + (size_t)r * K + c * 8);
        }
    };

    stage(0); CP_COMMIT();
    stage(1); CP_COMMIT();

    // per-lane ldmatrix row/chunk selectors (both operands non-trans)
    // A x4 matrices: (m0-7,k0-7) (m8-15,k0-7) (m0-7,k8-15) (m8-15,k8-15)
    const int rowA = (lane & 7) + ((lane >> 3) & 1) * 8;
    const int cselA = lane >> 4;
    // B x4 matrices: (n0-7,k0-7) (n0-7,k8-15) (n8-15,k0-7) (n8-15,k8-15)
    const int rowB = (lane & 7) + ((lane >> 4) << 3);
    const int cselB = (lane >> 3) & 1;

    for (int it = 0; it < KT; ++it) {
        CP_WAIT1();
        __syncthreads();
        if (it + 2 < KT) stage(it + 2);
        CP_COMMIT();

        const uint32_t aB = sb + (it % 3) * STAGE;
        const uint32_t bB = aB + 16384;
#pragma unroll
        for (int kk = 0; kk < 4; ++kk) {
            uint32_t af[4][4], bf[4][4];
#pragma unroll
            for (int mi = 0; mi < 4; ++mi) {
                const int r = wm * 64 + mi * 16 + rowA;
                const int ch = 2 * kk + cselA;
                LDSM_X4(af[mi], aB + r * 128 + ((ch ^ (r & 7)) << 4));
            }
#pragma unroll
            for (int np = 0; np < 4; ++np) {
                const int r = wn * 64 + np * 16 + rowB;
                const int ch = 2 * kk + cselB;
                LDSM_X4(bf[np], bB + r * 128 + ((ch ^ (r & 7)) << 4));
            }
#pragma unroll
            for (int mi = 0; mi < 4; ++mi)
#pragma unroll
                for (int ni = 0; ni < 8; ++ni)
                    mma_f16(acc[mi][ni], af[mi], &bf[ni >> 1][(ni & 1) * 2]);
        }
        __syncthreads();
    }

    // ---- epilogue ----
    const int mrow = m0 + wm * 64 + (lane >> 2);
    const int ncol = n0 + wn * 64 + 2 * (lane & 3);
#pragma unroll
    for (int mi = 0; mi < 4; ++mi) {
#pragma unroll
        for (int h = 0; h < 2; ++h) {
            const int m = mrow + mi * 16 + h * 8;
#pragma unroll
            for (int ni = 0; ni < 8; ++ni) {
                const int n = ncol + ni * 8;
                float x = acc[mi][ni][h * 2 + 0] * alpha;
                float y = acc[mi][ni][h * 2 + 1] * alpha;
                if (bias) { x += bias[n]; y += bias[n + 1]; }
                if (mask) {
                    const float2 mm = *(const float2*)
                        (mask + (size_t)m * ldMask + n);
                    x += mm.x; y += mm.y;
                }
                if (HOUT) {
                    *(__half2*)((__half*)Cv + (size_t)m * N + n) =
                        __floats2half2_rn(x, y);
                } else {
                    *(float2*)((float*)Cv + (size_t)m * N + n) =
                        make_float2(x, y);
                }
            }
        }
    }
}

// ---- wrappers -------------------------------------------------------------
__global__ __launch_bounds__(128, 2)
void proj_kernel(const __half* q, const __half* k, const __half* v,
                 const __half* Wq, const __half* Wk, const __half* Wv,
                 const float* bq, const float* bk, const float* bv,
                 __half* wq, __half* wk, __half* wv)
{
    const int z = blockIdx.z;
    const __half* A = z == 0 ? q : z == 1 ? k : v;
    const __half* B = z == 0 ? Wq : z == 1 ? Wk : Wv;
    const float* bi = z == 0 ? bq : z == 1 ? bk : bv;
    __half*      C = z == 0 ? wq : z == 1 ? wk : wv;
    gemm_core<true>(A, B, C, 1024, 1024, 1.f, bi, nullptr, 0,
                    blockIdx.y * 128, blockIdx.x * 128);
}

__global__ __launch_bounds__(128, 2)
void scores_kernel(const __half* wq, const __half* wk, __half* att,
                   const float* mask)
{
    const size_t pS = 2048ull * 1024ull, aS = 2048ull * 2048ull;
    gemm_core<true>(wq + blockIdx.z * pS, wk + blockIdx.z * pS,
                    att + blockIdx.z * aS, 2048, 1024, 1.f / 32.f,
                    nullptr, mask, 2048,
                    blockIdx.y * 128, blockIdx.x * 128);
}

__global__ __launch_bounds__(128, 2)
void out_kernel(const __half* att, const __half* wvT, float* out)
{
    const size_t aS = 2048ull * 2048ull, tS = 1024ull * 2048ull,
                 oS = 2048ull * 1024ull;
    gemm_core<false>(att + blockIdx.z * aS, wvT + blockIdx.z * tS,
                     out + blockIdx.z * oS, 1024, 2048, 1.f,
                     nullptr, nullptr, 0,
                     blockIdx.y * 128, blockIdx.x * 128);
}

// ---- fp32 -> fp16 convert -------------------------------------------------
__global__ __launch_bounds__(256)
void f2h_kernel(const float4* __restrict__ src, __half2* __restrict__ dst)
{
    const int i = blockIdx.x * 256 + threadIdx.x;
    const float4 v = src[i];
    dst[2 * i + 0] = __floats2half2_rn(v.x, v.y);
    dst[2 * i + 1] = __floats2half2_rn(v.z, v.w);
}

// ---- fp16 transpose: out[b][d][s] = in[b][s][d] ---------------------------
__global__ __launch_bounds__(256)
void transpose_h(const __half* __restrict__ in, __half* __restrict__ out)
{
    __shared__ __half tile[32][33];
    const int S = 2048, D = 1024;
    const size_t bo = (size_t)blockIdx.z * S * D;
    const int d0 = blockIdx.x * 32;
    const int s0 = blockIdx.y * 32;
    const int tx = threadIdx.x & 31;
    const int ty = threadIdx.x >> 5;
#pragma unroll
    for (int i = 0; i < 4; ++i)
        tile[ty + i * 8][tx] = in[bo + (size_t)(s0 + ty + i * 8) * D + d0 + tx];
    __syncthreads();
#pragma unroll
    for (int i = 0; i < 4; ++i)
        out[bo + (size_t)(d0 + ty + i * 8) * S + s0 + tx] = tile[tx][ty + i * 8];
}

// ---- softmax: rows of 2048 fp16, fp32 math --------------------------------
__global__ __launch_bounds__(256)
void softmax_h(__half* __restrict__ att)
{
    __half* p = att + (size_t)blockIdx.x * 2048;
    const int tid = threadIdx.x;
    const int lane = tid & 31;
    const int warp = tid >> 5;

    uint4 raw = ((const uint4*)p)[tid];      // 8 halves
    float2 f0 = __half22float2(*(__half2*)&raw.x);
    float2 f1 = __half22float2(*(__half2*)&raw.y);
    float2 f2 = __half22float2(*(__half2*)&raw.z);
    float2 f3 = __half22float2(*(__half2*)&raw.w);
    float x[8] = {f0.x, f0.y, f1.x, f1.y, f2.x, f2.y, f3.x, f3.y};

    __shared__ float sm[8];

    float mx = x[0];
#pragma unroll
    for (int i = 1; i < 8; ++i) mx = fmaxf(mx, x[i]);
#pragma unroll
    for (int o = 16; o > 0; o >>= 1)
        mx = fmaxf(mx, __shfl_xor_sync(0xffffffffu, mx, o));
    if (lane == 0) sm[warp] = mx;
    __syncthreads();
    if (tid == 0) {
        float t = sm[0];
#pragma unroll
        for (int i = 1; i < 8; ++i) t = fmaxf(t, sm[i]);
        sm[0] = t;
    }
    __syncthreads();
    mx = sm[0];
    __syncthreads();

    float s = 0.f;
#pragma unroll
    for (int i = 0; i < 8; ++i) { x[i] = __expf(x[i] - mx); s += x[i]; }
#pragma unroll
    for (int o = 16; o > 0; o >>= 1)
        s += __shfl_xor_sync(0xffffffffu, s, o);
    if (lane == 0) sm[warp] = s;
    __syncthreads();
    if (tid == 0) {
        float t = 0.f;
#pragma unroll
        for (int i = 0; i < 8; ++i) t += sm[i];
        sm[0] = t;
    }
    __syncthreads();
    const float inv = 1.f / sm[0];

    uint4 o;
    *(__half2*)&o.x = __floats2half2_rn(x[0] * inv, x[1] * inv);
    *(__half2*)&o.y = __floats2half2_rn(x[2] * inv, x[3] * inv);
    *(__half2*)&o.z = __floats2half2_rn(x[4] * inv, x[5] * inv);
    *(__half2*)&o.w = __floats2half2_rn(x[6] * inv, x[7] * inv);
    ((uint4*)p)[tid] = o;
}

// ---------------------------------------------------------------------------

extern "C" void kernel_launch(void* const* d_in, const int* in_sizes, int n_in,
                              void* d_out, int out_size)
{
    const float* q    = (const float*)d_in[0];
    const float* k    = (const float*)d_in[1];
    const float* v    = (const float*)d_in[2];
    const float* mask = (const float*)d_in[3];
    const float* Wq   = (const float*)d_in[4];
    const float* bq   = (const float*)d_in[5];
    const float* Wk   = (const float*)d_in[6];
    const float* bk   = (const float*)d_in[7];
    const float* Wv   = (const float*)d_in[8];
    const float* bv   = (const float*)d_in[9];
    float* out = (float*)d_out;

    __half *qh, *kh, *vh, *Wqh, *Wkh, *Wvh, *wqh, *wkh, *wvh, *wvT, *att;
    cudaGetSymbolAddress((void**)&qh,  g_qh);
    cudaGetSymbolAddress((void**)&kh,  g_kh);
    cudaGetSymbolAddress((void**)&vh,  g_vh);
    cudaGetSymbolAddress((void**)&Wqh, g_Wqh);
    cudaGetSymbolAddress((void**)&Wkh, g_Wkh);
    cudaGetSymbolAddress((void**)&Wvh, g_Wvh);
    cudaGetSymbolAddress((void**)&wqh, g_wqh);
    cudaGetSymbolAddress((void**)&wkh, g_wkh);
    cudaGetSymbolAddress((void**)&wvh, g_wvh);
    cudaGetSymbolAddress((void**)&wvT, g_wvT);
    cudaGetSymbolAddress((void**)&att, g_att);

    cudaFuncSetAttribute(proj_kernel,
        cudaFuncAttributeMaxDynamicSharedMemorySize, SMEMSZ);
    cudaFuncSetAttribute(scores_kernel,
        cudaFuncAttributeMaxDynamicSharedMemorySize, SMEMSZ);
    cudaFuncSetAttribute(out_kernel,
        cudaFuncAttributeMaxDynamicSharedMemorySize, SMEMSZ);

    const int B = 8, S = 2048, D = 1024;
    const int BSD4 = B * S * D / 4;      // 4.19M float4s
    const int DD4  = D * D / 4;

    // converts
    f2h_kernel<<<BSD4 / 256, 256>>>((const float4*)q, (__half2*)qh);
    f2h_kernel<<<BSD4 / 256, 256>>>((const float4*)k, (__half2*)kh);
    f2h_kernel<<<BSD4 / 256, 256>>>((const float4*)v, (__half2*)vh);
    f2h_kernel<<<DD4  / 256, 256>>>((const float4*)Wq, (__half2*)Wqh);
    f2h_kernel<<<DD4  / 256, 256>>>((const float4*)Wk, (__half2*)Wkh);
    f2h_kernel<<<DD4  / 256, 256>>>((const float4*)Wv, (__half2*)Wvh);

    // projections (z = 0,1,2)
    {
        dim3 grid(D / 128, B * S / 128, 3);
        proj_kernel<<<grid, 128, SMEMSZ>>>(qh, kh, vh, Wqh, Wkh, Wvh,
                                           bq, bk, bv, wqh, wkh, wvh);
    }

    // wvT
    {
        dim3 grid(D / 32, S / 32, B);
        transpose_h<<<grid, 256>>>(wvh, wvT);
    }

    // scores
    {
        dim3 grid(S / 128, S / 128, B);
        scores_kernel<<<grid, 128, SMEMSZ>>>(wqh, wkh, att, mask);
    }

    // softmax
    softmax_h<<<B * S, 256>>>(att);

    // output
    {
        dim3 grid(D / 128, S / 128, B);
        out_kernel<<<grid, 128, SMEMSZ>>>(att, wvT, out);
    }
}

// round 11
// speedup vs baseline: 7.7358x; 1.0251x over previous
#include <cuda_runtime.h>
#include <cuda_fp16.h>
#include <cstdint>

// ===========================================================================
// B=8, S=2048, D=1024 attention. fp16 mma.sync(m16n8k16) + cp.async pipeline.
// R9: register double-buffered fragments across kk; single barrier per chunk.
// ===========================================================================

static __device__ __half g_qh [8ull * 2048ull * 1024ull];
static __device__ __half g_kh [8ull * 2048ull * 1024ull];
static __device__ __half g_vh [8ull * 2048ull * 1024ull];
static __device__ __half g_Wqh[1024ull * 1024ull];
static __device__ __half g_Wkh[1024ull * 1024ull];
static __device__ __half g_Wvh[1024ull * 1024ull];
static __device__ __half g_wqh[8ull * 2048ull * 1024ull];
static __device__ __half g_wkh[8ull * 2048ull * 1024ull];
static __device__ __half g_wvh[8ull * 2048ull * 1024ull];
static __device__ __half g_wvT[8ull * 1024ull * 2048ull];
static __device__ __half g_att[8ull * 2048ull * 2048ull];

__device__ __forceinline__ uint32_t smem_u32(const void* p) {
    uint32_t a;
    asm("{ .reg .u64 t; cvta.to.shared.u64 t, %1; cvt.u32.u64 %0, t; }"
        : "=r"(a) : "l"(p));
    return a;
}

__device__ __forceinline__ void cp16(uint32_t s, const void* g) {
    asm volatile("cp.async.cg.shared.global [%0], [%1], 16;" :: "r"(s), "l"(g));
}
#define CP_COMMIT() asm volatile("cp.async.commit_group;" ::: "memory")
#define CP_WAIT1()  asm volatile("cp.async.wait_group 1;" ::: "memory")

#define LDSM_X4(r, a)                                                        \
    asm volatile("ldmatrix.sync.aligned.m8n8.x4.shared.b16 {%0,%1,%2,%3}, [%4];" \
        : "=r"((r)[0]), "=r"((r)[1]), "=r"((r)[2]), "=r"((r)[3]) : "r"(a))

__device__ __forceinline__ void mma_f16(float* d, const uint32_t* a,
                                        const uint32_t* b) {
    asm volatile(
        "mma.sync.aligned.m16n8k16.row.col.f32.f16.f16.f32 "
        "{%0,%1,%2,%3}, {%4,%5,%6,%7}, {%8,%9}, {%0,%1,%2,%3};\n"
        : "+f"(d[0]), "+f"(d[1]), "+f"(d[2]), "+f"(d[3])
        : "r"(a[0]), "r"(a[1]), "r"(a[2]), "r"(a[3]), "r"(b[0]), "r"(b[1]));
}

// SMEM: 3 stages x (A 16KB + B 16KB) = 96 KB
static constexpr int STAGE  = 32768;
static constexpr int SMEMSZ = 3 * STAGE;

// ---------------------------------------------------------------------------
// Core: C = alpha*(A @ B^T) [+bias cols] [+mask]; A:[*,K] B:[*,K] fp16 NT.
// CTA 128x128, warp 64x64, K-chunk 64, 3-stage cp.async ring.
// smem row layout: 128 rows x 128B (64 halves), 16B chunk c at (c ^ (row&7)).
// Both operands via NON-trans ldmatrix (B stored [n][k] == col-major KxN).
// Fragments double-buffered in registers across the 4 kk sub-steps.
// ---------------------------------------------------------------------------
template <bool HOUT>
__device__ __forceinline__ void gemm_core(
    const __half* __restrict__ A, const __half* __restrict__ B,
    void* __restrict__ Cv, int N, int K, float alpha,
    const float* __restrict__ bias,
    const float* __restrict__ mask, int ldMask,
    int m0, int n0)
{
    extern __shared__ char smem[];
    const uint32_t sb = smem_u32(smem);
    const int tid  = threadIdx.x;
    const int lane = tid & 31;
    const int wid  = tid >> 5;
    const int wm   = wid & 1;
    const int wn   = wid >> 1;

    float acc[4][8][4];
#pragma unroll
    for (int i = 0; i < 4; ++i)
#pragma unroll
        for (int j = 0; j < 8; ++j)
#pragma unroll
            for (int l = 0; l < 4; ++l) acc[i][j][l] = 0.f;

    const int KT = K >> 6;

    auto stage = [&](int it) {
        const int buf = it % 3;
        const uint32_t sA = sb + buf * STAGE;
        const uint32_t sB = sA + 16384;
        const __half* Ab = A + (size_t)m0 * K + it * 64;
        const __half* Bb = B + (size_t)n0 * K + it * 64;
#pragma unroll
        for (int i = 0; i < 8; ++i) {
            const int f = tid + (i << 7);
            const int r = f >> 3, c = f & 7;
            const uint32_t off = r * 128 + ((c ^ (r & 7)) << 4);
            cp16(sA + off, Ab + (size_t)r * K + c * 8);
            cp16(sB + off, Bb + (size_t)r * K + c * 8);
        }
    };

    stage(0); CP_COMMIT();
    stage(1); CP_COMMIT();

    // per-lane ldmatrix row/chunk selectors (both operands non-trans)
    const int rowA = (lane & 7) + ((lane >> 3) & 1) * 8;
    const int cselA = lane >> 4;
    const int rowB = (lane & 7) + ((lane >> 4) << 3);
    const int cselB = (lane >> 3) & 1;

    uint32_t af[2][4][4], bf[2][4][4];

    for (int it = 0; it < KT; ++it) {
        CP_WAIT1();
        __syncthreads();
        if (it + 2 < KT) stage(it + 2);
        CP_COMMIT();

        const uint32_t aB = sb + (it % 3) * STAGE;
        const uint32_t bB = aB + 16384;

        // prime kk = 0 fragments
#pragma unroll
        for (int mi = 0; mi < 4; ++mi) {
            const int r = wm * 64 + mi * 16 + rowA;
            LDSM_X4(af[0][mi], aB + r * 128 + ((cselA ^ (r & 7)) << 4));
        }
#pragma unroll
        for (int np = 0; np < 4; ++np) {
            const int r = wn * 64 + np * 16 + rowB;
            LDSM_X4(bf[0][np], bB + r * 128 + ((cselB ^ (r & 7)) << 4));
        }

#pragma unroll
        for (int kk = 0; kk < 4; ++kk) {
            const int cur = kk & 1, nxt = cur ^ 1;
            if (kk < 3) {                // prefetch kk+1 while mma'ing kk
                const int ch = 2 * (kk + 1);
#pragma unroll
                for (int mi = 0; mi < 4; ++mi) {
                    const int r = wm * 64 + mi * 16 + rowA;
                    LDSM_X4(af[nxt][mi],
                            aB + r * 128 + (((ch + cselA) ^ (r & 7)) << 4));
                }
#pragma unroll
                for (int np = 0; np < 4; ++np) {
                    const int r = wn * 64 + np * 16 + rowB;
                    LDSM_X4(bf[nxt][np],
                            bB + r * 128 + (((ch + cselB) ^ (r & 7)) << 4));
                }
            }
#pragma unroll
            for (int mi = 0; mi < 4; ++mi)
#pragma unroll
                for (int ni = 0; ni < 8; ++ni)
                    mma_f16(acc[mi][ni], af[cur][mi],
                            &bf[cur][ni >> 1][(ni & 1) * 2]);
        }
        // no trailing barrier: next iteration's CP_WAIT1+__syncthreads orders
        // these smem reads against the stage() that overwrites this buffer.
    }

    // ---- epilogue ----
    const int mrow = m0 + wm * 64 + (lane >> 2);
    const int ncol = n0 + wn * 64 + 2 * (lane & 3);
#pragma unroll
    for (int mi = 0; mi < 4; ++mi) {
#pragma unroll
        for (int h = 0; h < 2; ++h) {
            const int m = mrow + mi * 16 + h * 8;
#pragma unroll
            for (int ni = 0; ni < 8; ++ni) {
                const int n = ncol + ni * 8;
                float x = acc[mi][ni][h * 2 + 0] * alpha;
                float y = acc[mi][ni][h * 2 + 1] * alpha;
                if (bias) { x += bias[n]; y += bias[n + 1]; }
                if (mask) {
                    const float2 mm = *(const float2*)
                        (mask + (size_t)m * ldMask + n);
                    x += mm.x; y += mm.y;
                }
                if (HOUT) {
                    *(__half2*)((__half*)Cv + (size_t)m * N + n) =
                        __floats2half2_rn(x, y);
                } else {
                    *(float2*)((float*)Cv + (size_t)m * N + n) =
                        make_float2(x, y);
                }
            }
        }
    }
}

// ---- wrappers -------------------------------------------------------------
__global__ __launch_bounds__(128, 2)
void proj_kernel(const __half* q, const __half* k, const __half* v,
                 const __half* Wq, const __half* Wk, const __half* Wv,
                 const float* bq, const float* bk, const float* bv,
                 __half* wq, __half* wk, __half* wv)
{
    const int z = blockIdx.z;
    const __half* A = z == 0 ? q : z == 1 ? k : v;
    const __half* B = z == 0 ? Wq : z == 1 ? Wk : Wv;
    const float* bi = z == 0 ? bq : z == 1 ? bk : bv;
    __half*      C = z == 0 ? wq : z == 1 ? wk : wv;
    gemm_core<true>(A, B, C, 1024, 1024, 1.f, bi, nullptr, 0,
                    blockIdx.y * 128, blockIdx.x * 128);
}

__global__ __launch_bounds__(128, 2)
void scores_kernel(const __half* wq, const __half* wk, __half* att,
                   const float* mask)
{
    const size_t pS = 2048ull * 1024ull, aS = 2048ull * 2048ull;
    gemm_core<true>(wq + blockIdx.z * pS, wk + blockIdx.z * pS,
                    att + blockIdx.z * aS, 2048, 1024, 1.f / 32.f,
                    nullptr, mask, 2048,
                    blockIdx.y * 128, blockIdx.x * 128);
}

__global__ __launch_bounds__(128, 2)
void out_kernel(const __half* att, const __half* wvT, float* out)
{
    const size_t aS = 2048ull * 2048ull, tS = 1024ull * 2048ull,
                 oS = 2048ull * 1024ull;
    gemm_core<false>(att + blockIdx.z * aS, wvT + blockIdx.z * tS,
                     out + blockIdx.z * oS, 1024, 2048, 1.f,
                     nullptr, nullptr, 0,
                     blockIdx.y * 128, blockIdx.x * 128);
}

// ---- fp32 -> fp16 convert -------------------------------------------------
__global__ __launch_bounds__(256)
void f2h_kernel(const float4* __restrict__ src, __half2* __restrict__ dst)
{
    const int i = blockIdx.x * 256 + threadIdx.x;
    const float4 v = src[i];
    dst[2 * i + 0] = __floats2half2_rn(v.x, v.y);
    dst[2 * i + 1] = __floats2half2_rn(v.z, v.w);
}

// ---- fp16 transpose: out[b][d][s] = in[b][s][d] ---------------------------
__global__ __launch_bounds__(256)
void transpose_h(const __half* __restrict__ in, __half* __restrict__ out)
{
    __shared__ __half tile[32][33];
    const int S = 2048, D = 1024;
    const size_t bo = (size_t)blockIdx.z * S * D;
    const int d0 = blockIdx.x * 32;
    const int s0 = blockIdx.y * 32;
    const int tx = threadIdx.x & 31;
    const int ty = threadIdx.x >> 5;
#pragma unroll
    for (int i = 0; i < 4; ++i)
        tile[ty + i * 8][tx] = in[bo + (size_t)(s0 + ty + i * 8) * D + d0 + tx];
    __syncthreads();
#pragma unroll
    for (int i = 0; i < 4; ++i)
        out[bo + (size_t)(d0 + ty + i * 8) * S + s0 + tx] = tile[tx][ty + i * 8];
}

// ---- softmax: rows of 2048 fp16, fp32 math --------------------------------
__global__ __launch_bounds__(256)
void softmax_h(__half* __restrict__ att)
{
    __half* p = att + (size_t)blockIdx.x * 2048;
    const int tid = threadIdx.x;
    const int lane = tid & 31;
    const int warp = tid >> 5;

    uint4 raw = ((const uint4*)p)[tid];      // 8 halves
    float2 f0 = __half22float2(*(__half2*)&raw.x);
    float2 f1 = __half22float2(*(__half2*)&raw.y);
    float2 f2 = __half22float2(*(__half2*)&raw.z);
    float2 f3 = __half22float2(*(__half2*)&raw.w);
    float x[8] = {f0.x, f0.y, f1.x, f1.y, f2.x, f2.y, f3.x, f3.y};

    __shared__ float sm[8];

    float mx = x[0];
#pragma unroll
    for (int i = 1; i < 8; ++i) mx = fmaxf(mx, x[i]);
#pragma unroll
    for (int o = 16; o > 0; o >>= 1)
        mx = fmaxf(mx, __shfl_xor_sync(0xffffffffu, mx, o));
    if (lane == 0) sm[warp] = mx;
    __syncthreads();
    if (tid == 0) {
        float t = sm[0];
#pragma unroll
        for (int i = 1; i < 8; ++i) t = fmaxf(t, sm[i]);
        sm[0] = t;
    }
    __syncthreads();
    mx = sm[0];
    __syncthreads();

    float s = 0.f;
#pragma unroll
    for (int i = 0; i < 8; ++i) { x[i] = __expf(x[i] - mx); s += x[i]; }
#pragma unroll
    for (int o = 16; o > 0; o >>= 1)
        s += __shfl_xor_sync(0xffffffffu, s, o);
    if (lane == 0) sm[warp] = s;
    __syncthreads();
    if (tid == 0) {
        float t = 0.f;
#pragma unroll
        for (int i = 0; i < 8; ++i) t += sm[i];
        sm[0] = t;
    }
    __syncthreads();
    const float inv = 1.f / sm[0];

    uint4 o;
    *(__half2*)&o.x = __floats2half2_rn(x[0] * inv, x[1] * inv);
    *(__half2*)&o.y = __floats2half2_rn(x[2] * inv, x[3] * inv);
    *(__half2*)&o.z = __floats2half2_rn(x[4] * inv, x[5] * inv);
    *(__half2*)&o.w = __floats2half2_rn(x[6] * inv, x[7] * inv);
    ((uint4*)p)[tid] = o;
}

// ---------------------------------------------------------------------------

extern "C" void kernel_launch(void* const* d_in, const int* in_sizes, int n_in,
                              void* d_out, int out_size)
{
    const float* q    = (const float*)d_in[0];
    const float* k    = (const float*)d_in[1];
    const float* v    = (const float*)d_in[2];
    const float* mask = (const float*)d_in[3];
    const float* Wq   = (const float*)d_in[4];
    const float* bq   = (const float*)d_in[5];
    const float* Wk   = (const float*)d_in[6];
    const float* bk   = (const float*)d_in[7];
    const float* Wv   = (const float*)d_in[8];
    const float* bv   = (const float*)d_in[9];
    float* out = (float*)d_out;

    __half *qh, *kh, *vh, *Wqh, *Wkh, *Wvh, *wqh, *wkh, *wvh, *wvT, *att;
    cudaGetSymbolAddress((void**)&qh,  g_qh);
    cudaGetSymbolAddress((void**)&kh,  g_kh);
    cudaGetSymbolAddress((void**)&vh,  g_vh);
    cudaGetSymbolAddress((void**)&Wqh, g_Wqh);
    cudaGetSymbolAddress((void**)&Wkh, g_Wkh);
    cudaGetSymbolAddress((void**)&Wvh, g_Wvh);
    cudaGetSymbolAddress((void**)&wqh, g_wqh);
    cudaGetSymbolAddress((void**)&wkh, g_wkh);
    cudaGetSymbolAddress((void**)&wvh, g_wvh);
    cudaGetSymbolAddress((void**)&wvT, g_wvT);
    cudaGetSymbolAddress((void**)&att, g_att);

    cudaFuncSetAttribute(proj_kernel,
        cudaFuncAttributeMaxDynamicSharedMemorySize, SMEMSZ);
    cudaFuncSetAttribute(scores_kernel,
        cudaFuncAttributeMaxDynamicSharedMemorySize, SMEMSZ);
    cudaFuncSetAttribute(out_kernel,
        cudaFuncAttributeMaxDynamicSharedMemorySize, SMEMSZ);

    const int B = 8, S = 2048, D = 1024;
    const int BSD4 = B * S * D / 4;
    const int DD4  = D * D / 4;

    // converts
    f2h_kernel<<<BSD4 / 256, 256>>>((const float4*)q, (__half2*)qh);
    f2h_kernel<<<BSD4 / 256, 256>>>((const float4*)k, (__half2*)kh);
    f2h_kernel<<<BSD4 / 256, 256>>>((const float4*)v, (__half2*)vh);
    f2h_kernel<<<DD4  / 256, 256>>>((const float4*)Wq, (__half2*)Wqh);
    f2h_kernel<<<DD4  / 256, 256>>>((const float4*)Wk, (__half2*)Wkh);
    f2h_kernel<<<DD4  / 256, 256>>>((const float4*)Wv, (__half2*)Wvh);

    // projections (z = 0,1,2)
    {
        dim3 grid(D / 128, B * S / 128, 3);
        proj_kernel<<<grid, 128, SMEMSZ>>>(qh, kh, vh, Wqh, Wkh, Wvh,
                                           bq, bk, bv, wqh, wkh, wvh);
    }

    // wvT
    {
        dim3 grid(D / 32, S / 32, B);
        transpose_h<<<grid, 256>>>(wvh, wvT);
    }

    // scores
    {
        dim3 grid(S / 128, S / 128, B);
        scores_kernel<<<grid, 128, SMEMSZ>>>(wqh, wkh, att, mask);
    }

    // softmax
    softmax_h<<<B * S, 256>>>(att);

    // output
    {
        dim3 grid(D / 128, S / 128, B);
        out_kernel<<<grid, 128, SMEMSZ>>>(att, wvT, out);
    }
}